// round 1
// baseline (speedup 1.0000x reference)
#include <cuda_runtime.h>
#include <cuda_bf16.h>
#include <math.h>

// Problem constants (fixed by reference)
#define NTOK   8192
#define HIDDEN 2048
#define FFN    2048
#define NEXP   8
#define TOPK   2
#define M_TOT  (NTOK * TOPK)      // 16384 scattered rows
#define CAP    (M_TOT / NEXP)     // 2048 rows per expert

// Scratch: __device__ globals (no allocation allowed in kernel_launch)
__device__ float g_h[(size_t)M_TOT * FFN];      // fc1 output (post-GELU), 128 MB
__device__ float g_y[(size_t)M_TOT * HIDDEN];   // fc2 output, 128 MB
__device__ int   g_gather[M_TOT];               // inverse of scatter_index

// Tiling
constexpr int BM = 128, BN = 128, BK = 16;
constexpr int TM = 8, TN = 8;
constexpr int PAD = 2;            // smem row pad -> conflict-free transposed stores
constexpr int THREADS = 256;      // (BM/TM)*(BN/TN)

// ---------------------------------------------------------------------------
// gather[scatter[p]] = p / TOPK  (which token feeds expert-buffer row r)
__global__ void build_gather_kernel(const int* __restrict__ scat) {
    int p = blockIdx.x * blockDim.x + threadIdx.x;
    if (p < M_TOT) g_gather[scat[p]] = p / TOPK;
}

// ---------------------------------------------------------------------------
// packed f32x2 helpers (FFMA2 is PTX-only; ptxas never auto-fuses it)
__device__ __forceinline__ unsigned long long pack_dup(float a) {
    unsigned long long v;
    unsigned int au = __float_as_uint(a);
    asm("mov.b64 %0, {%1, %1};" : "=l"(v) : "r"(au));
    return v;
}
__device__ __forceinline__ void unpack2(unsigned long long v, float& lo, float& hi) {
    unsigned int l, h;
    asm("mov.b64 {%0, %1}, %2;" : "=r"(l), "=r"(h) : "l"(v));
    lo = __uint_as_float(l);
    hi = __uint_as_float(h);
}
__device__ __forceinline__ void fma2(unsigned long long& acc,
                                     unsigned long long a, unsigned long long b) {
    asm("fma.rn.f32x2 %0, %1, %2, %0;" : "+l"(acc) : "l"(a), "l"(b));
}

// ---------------------------------------------------------------------------
// C[r, n] = sum_k A[row(r), k] * W[e, n, k]   (both operands K-major: C = A @ W^T)
// GATHER: A row = inputs_shard[g_gather[r]]  (fc1);  else A row = A[r] (fc2)
// GELU:   exact gelu on output (fc1)
template <bool GATHER, bool GELU>
__global__ __launch_bounds__(THREADS, 2)
void gemm_nt_kernel(const float* __restrict__ A, const float* __restrict__ W,
                    float* __restrict__ C, int K, int N) {
    __shared__ float As[BK][BM + PAD];
    __shared__ float Bs[BK][BN + PAD];

    const int e       = blockIdx.z;
    const int rowTile = blockIdx.y * BM;
    const int colTile = blockIdx.x * BN;
    const int tid     = threadIdx.x;
    const int grow0   = e * CAP + rowTile;      // base row in expert-sorted space

    // ---- loader mapping: 128 rows x 16 cols per tile, 2 float4 per thread
    const int lr = tid >> 2;            // 0..63
    const int lc = (tid & 3) * 4;       // 0,4,8,12

    const float* aptr0;
    const float* aptr1;
    if (GATHER) {
        aptr0 = A + (size_t)g_gather[grow0 + lr]      * K;
        aptr1 = A + (size_t)g_gather[grow0 + lr + 64] * K;
    } else {
        aptr0 = A + (size_t)(grow0 + lr)      * K;
        aptr1 = A + (size_t)(grow0 + lr + 64) * K;
    }
    const float* wptr0 = W + ((size_t)e * N + colTile + lr) * K;
    const float* wptr1 = wptr0 + (size_t)64 * K;

    // ---- compute mapping: 16x16 thread grid, 8x8 outputs each
    const int trow = (tid >> 4) * TM;   // 0..120
    const int tcol = (tid & 15) * TN;   // 0..120

    unsigned long long acc[TM][TN / 2];
#pragma unroll
    for (int i = 0; i < TM; i++)
#pragma unroll
        for (int j = 0; j < TN / 2; j++) acc[i][j] = 0ull;

    for (int k0 = 0; k0 < K; k0 += BK) {
        // global -> smem (transposed, conflict-free with PAD=2)
        float4 a0 = *(const float4*)(aptr0 + k0 + lc);
        float4 a1 = *(const float4*)(aptr1 + k0 + lc);
        float4 b0 = *(const float4*)(wptr0 + k0 + lc);
        float4 b1 = *(const float4*)(wptr1 + k0 + lc);

        As[lc + 0][lr] = a0.x; As[lc + 1][lr] = a0.y;
        As[lc + 2][lr] = a0.z; As[lc + 3][lr] = a0.w;
        As[lc + 0][lr + 64] = a1.x; As[lc + 1][lr + 64] = a1.y;
        As[lc + 2][lr + 64] = a1.z; As[lc + 3][lr + 64] = a1.w;
        Bs[lc + 0][lr] = b0.x; Bs[lc + 1][lr] = b0.y;
        Bs[lc + 2][lr] = b0.z; Bs[lc + 3][lr] = b0.w;
        Bs[lc + 0][lr + 64] = b1.x; Bs[lc + 1][lr + 64] = b1.y;
        Bs[lc + 2][lr + 64] = b1.z; Bs[lc + 3][lr + 64] = b1.w;
        __syncthreads();

#pragma unroll
        for (int kk = 0; kk < BK; kk++) {
            unsigned long long a2[TM];
            unsigned long long b2[TN / 2];
#pragma unroll
            for (int i = 0; i < TM; i += 2) {
                float2 v = *(const float2*)&As[kk][trow + i];
                a2[i]     = pack_dup(v.x);
                a2[i + 1] = pack_dup(v.y);
            }
#pragma unroll
            for (int j = 0; j < TN / 2; j++)
                b2[j] = *(const unsigned long long*)&Bs[kk][tcol + 2 * j];
#pragma unroll
            for (int i = 0; i < TM; i++)
#pragma unroll
                for (int j = 0; j < TN / 2; j++)
                    fma2(acc[i][j], a2[i], b2[j]);
        }
        __syncthreads();
    }

    // ---- epilogue
#pragma unroll
    for (int i = 0; i < TM; i++) {
        float vals[TN];
#pragma unroll
        for (int j = 0; j < TN / 2; j++)
            unpack2(acc[i][j], vals[2 * j], vals[2 * j + 1]);
        if (GELU) {
#pragma unroll
            for (int j = 0; j < TN; j++) {
                float x = vals[j];
                vals[j] = 0.5f * x * (1.0f + erff(x * 0.7071067811865476f));
            }
        }
        float* crow = C + (size_t)(grow0 + trow + i) * N + colTile + tcol;
        *(float4*)(crow)     = make_float4(vals[0], vals[1], vals[2], vals[3]);
        *(float4*)(crow + 4) = make_float4(vals[4], vals[5], vals[6], vals[7]);
    }
}

// ---------------------------------------------------------------------------
// out[t, :] = y[scatter[t,0], :] + y[scatter[t,1], :]
__global__ void combine_kernel(const int* __restrict__ scat, float* __restrict__ out) {
    int idx = blockIdx.x * blockDim.x + threadIdx.x;   // over NTOK * HIDDEN/4
    int t  = idx / (HIDDEN / 4);
    int c4 = (idx % (HIDDEN / 4)) * 4;
    int s0 = scat[t * TOPK + 0];
    int s1 = scat[t * TOPK + 1];
    float4 v0 = *(const float4*)(g_y + (size_t)s0 * HIDDEN + c4);
    float4 v1 = *(const float4*)(g_y + (size_t)s1 * HIDDEN + c4);
    *(float4*)(out + (size_t)t * HIDDEN + c4) =
        make_float4(v0.x + v1.x, v0.y + v1.y, v0.z + v1.z, v0.w + v1.w);
}

// ---------------------------------------------------------------------------
extern "C" void kernel_launch(void* const* d_in, const int* in_sizes, int n_in,
                              void* d_out, int out_size) {
    const float* x    = (const float*)d_in[0];   // [NTOK, HIDDEN]
    const float* w1   = (const float*)d_in[1];   // [E, FFN, HIDDEN]
    const float* w2   = (const float*)d_in[2];   // [E, HIDDEN, FFN]
    const int*   scat = (const int*)d_in[3];     // [NTOK, TOPK]
    float* out = (float*)d_out;                  // [NTOK, HIDDEN]

    float* h_buf = nullptr;
    float* y_buf = nullptr;
    cudaGetSymbolAddress((void**)&h_buf, g_h);
    cudaGetSymbolAddress((void**)&y_buf, g_y);

    build_gather_kernel<<<M_TOT / 256, 256>>>(scat);

    dim3 grid1(FFN / BN, CAP / BM, NEXP);
    gemm_nt_kernel<true, true><<<grid1, THREADS>>>(x, w1, h_buf, HIDDEN, FFN);

    dim3 grid2(HIDDEN / BN, CAP / BM, NEXP);
    gemm_nt_kernel<false, false><<<grid2, THREADS>>>(h_buf, w2, y_buf, FFN, HIDDEN);

    combine_kernel<<<(NTOK * (HIDDEN / 4)) / 256, 256>>>(scat, out);
}

// round 3
// speedup vs baseline: 2.8180x; 2.8180x over previous
#include <cuda_runtime.h>
#include <cuda_bf16.h>
#include <math.h>
#include <stdint.h>

// ---------------------------------------------------------------- constants
#define NTOK   8192
#define HIDDEN 2048
#define NEXP   8
#define TOPK   2
#define M_TOT  (NTOK * TOPK)      // 16384
#define CAP    (M_TOT / NEXP)     // 2048
#define KDIM   2048
#define NDIM   2048

constexpr int BM = 128, BN = 128, BK = 32;
constexpr int NS = 3;                          // pipeline stages
constexpr int NITER = KDIM / BK;               // 64
constexpr uint32_t TILE_BYTES  = 128 * 64;     // 8 KB: 128 rows x 32 bf16
constexpr uint32_t STAGE_BYTES = 4 * TILE_BYTES;   // Ah, Al, Bh, Bl = 32 KB
constexpr uint32_t SMEM_SZ     = NS * STAGE_BYTES; // 96 KB

// ---------------------------------------------------------------- scratch
__device__ __align__(1024) __nv_bfloat16 g_xs_hi[(size_t)M_TOT * KDIM];
__device__ __align__(1024) __nv_bfloat16 g_xs_lo[(size_t)M_TOT * KDIM];
__device__ __align__(1024) __nv_bfloat16 g_w1_hi[(size_t)NEXP * NDIM * KDIM];
__device__ __align__(1024) __nv_bfloat16 g_w1_lo[(size_t)NEXP * NDIM * KDIM];
__device__ __align__(1024) __nv_bfloat16 g_w2_hi[(size_t)NEXP * NDIM * KDIM];
__device__ __align__(1024) __nv_bfloat16 g_w2_lo[(size_t)NEXP * NDIM * KDIM];
__device__ __align__(1024) __nv_bfloat16 g_h_hi[(size_t)M_TOT * NDIM];
__device__ __align__(1024) __nv_bfloat16 g_h_lo[(size_t)M_TOT * NDIM];
__device__ __align__(1024) float         g_y[(size_t)M_TOT * HIDDEN];

// ---------------------------------------------------------------- helpers
__device__ __forceinline__ uint32_t smem_u32(const void* p) {
    uint32_t a;
    asm("{ .reg .u64 t; cvta.to.shared.u64 t, %1; cvt.u32.u64 %0, t; }"
        : "=r"(a) : "l"(p));
    return a;
}
__device__ __forceinline__ uint32_t sw128(uint32_t off) {
    return off ^ ((off >> 3) & 0x70);
}
__device__ __forceinline__ void cp16(uint32_t dst, const void* src) {
    asm volatile("cp.async.cg.shared.global [%0], [%1], 16;"
                 :: "r"(dst), "l"(src));
}
__device__ __forceinline__ void cp_commit() {
    asm volatile("cp.async.commit_group;");
}
template <int N>
__device__ __forceinline__ void cp_wait() {
    asm volatile("cp.async.wait_group %0;" :: "n"(N));
}
__device__ __forceinline__ void ldsm4(uint32_t* r, uint32_t addr) {
    asm volatile("ldmatrix.sync.aligned.m8n8.x4.shared.b16 {%0,%1,%2,%3}, [%4];"
                 : "=r"(r[0]), "=r"(r[1]), "=r"(r[2]), "=r"(r[3]) : "r"(addr));
}
__device__ __forceinline__ void mma_bf16(float* c, const uint32_t* a,
                                         const uint32_t* b) {
    asm volatile(
        "mma.sync.aligned.m16n8k16.row.col.f32.bf16.bf16.f32 "
        "{%0,%1,%2,%3},{%4,%5,%6,%7},{%8,%9},{%0,%1,%2,%3};"
        : "+f"(c[0]), "+f"(c[1]), "+f"(c[2]), "+f"(c[3])
        : "r"(a[0]), "r"(a[1]), "r"(a[2]), "r"(a[3]), "r"(b[0]), "r"(b[1]));
}

// ---------------------------------------------------------------- GEMM
// C[r,n] = sum_k A[r,k]*W[e,n,k]  via bf16 3-term split, fp32 accumulate.
template <bool GELU>
__global__ void __launch_bounds__(256, 1)
gemm_mma(const __nv_bfloat16* __restrict__ Ah, const __nv_bfloat16* __restrict__ Al,
         const __nv_bfloat16* __restrict__ Wh, const __nv_bfloat16* __restrict__ Wl,
         __nv_bfloat16* __restrict__ out_hi, __nv_bfloat16* __restrict__ out_lo,
         float* __restrict__ out_f32) {
    extern __shared__ __align__(1024) char smem[];
    const uint32_t sb = smem_u32(smem);
    const int tid  = threadIdx.x;
    const int lane = tid & 31;
    const int w    = tid >> 5;
    const int wm   = w & 1;       // M half (64 rows)
    const int wn   = w >> 1;      // N quarter (32 cols)
    const int grow0 = blockIdx.y * BM;
    const int gcol0 = blockIdx.x * BN;
    const int e     = grow0 / CAP;

    // ---- loader mapping: thread -> tile (Ah/Al/Bh/Bl), 8 chunks of 16B
    const int ltile = tid >> 6;          // 0..3
    const int lch   = tid & 63;          // chunk within first 16 rows
    const int lr0   = lch >> 2;          // row 0..15
    const int lc    = lch & 3;           // 16B chunk 0..3
    const uint32_t soff0 = (uint32_t)ltile * TILE_BYTES + sw128(lr0 * 64 + lc * 16);
    const __nv_bfloat16* gbase;
    if (ltile == 0)      gbase = Ah + (size_t)(grow0 + lr0) * KDIM + lc * 8;
    else if (ltile == 1) gbase = Al + (size_t)(grow0 + lr0) * KDIM + lc * 8;
    else if (ltile == 2) gbase = Wh + ((size_t)e * NDIM + gcol0 + lr0) * KDIM + lc * 8;
    else                 gbase = Wl + ((size_t)e * NDIM + gcol0 + lr0) * KDIM + lc * 8;

    // ---- ldmatrix per-lane offsets
    // A: lanes 0-15 khalf0 rows 0..15, lanes 16-31 khalf1
    const int ar  = lane & 15;
    const int akh = lane >> 4;
    const uint32_t aoff = sw128(ar * 64 + akh * 16);     // + wm*4096 + mi*1024
    // B: rn = lane&7, h = (lane>>3)&1, gsel = lane>>4 (0/1); two n16 groups
    const int brn = lane & 7;
    const int bh  = (lane >> 3) & 1;
    const int bgs = lane >> 4;
    const int nrow0 = wn * 32 + bgs * 8 + brn;
    const uint32_t boff0 = sw128(nrow0 * 64 + bh * 16);
    const uint32_t boff1 = sw128((nrow0 + 16) * 64 + bh * 16);

    float acc[4][4][4];
#pragma unroll
    for (int i = 0; i < 4; i++)
#pragma unroll
        for (int j = 0; j < 4; j++)
#pragma unroll
            for (int k = 0; k < 4; k++) acc[i][j][k] = 0.f;

    auto load_stage = [&](int it) {
        if (it < NITER) {
            const uint32_t dst = sb + (uint32_t)(it % NS) * STAGE_BYTES + soff0;
            const __nv_bfloat16* src = gbase + it * BK;
#pragma unroll
            for (int i = 0; i < 8; i++)
                cp16(dst + i * 1024, src + (size_t)i * 16 * KDIM);
        }
        cp_commit();
    };

    load_stage(0);
    load_stage(1);

    for (int it = 0; it < NITER; it++) {
        cp_wait<1>();
        __syncthreads();
        load_stage(it + 2);

        const uint32_t base = sb + (uint32_t)(it % NS) * STAGE_BYTES;
#pragma unroll
        for (int kk = 0; kk < 2; kk++) {
            const uint32_t kx = (uint32_t)kk << 5;
            uint32_t aH[4][4], aL[4][4], bH[4][2], bL[4][2];
            const uint32_t aaddr = base + wm * 4096 + (aoff ^ kx);
#pragma unroll
            for (int mi = 0; mi < 4; mi++) {
                ldsm4(aH[mi], aaddr + mi * 1024);
                ldsm4(aL[mi], aaddr + TILE_BYTES + mi * 1024);
            }
            {
                uint32_t t0[4], t1[4];
                ldsm4(t0, base + 2 * TILE_BYTES + (boff0 ^ kx));
                bH[0][0] = t0[0]; bH[0][1] = t0[1];
                bH[1][0] = t0[2]; bH[1][1] = t0[3];
                ldsm4(t1, base + 2 * TILE_BYTES + (boff1 ^ kx));
                bH[2][0] = t1[0]; bH[2][1] = t1[1];
                bH[3][0] = t1[2]; bH[3][1] = t1[3];
                ldsm4(t0, base + 3 * TILE_BYTES + (boff0 ^ kx));
                bL[0][0] = t0[0]; bL[0][1] = t0[1];
                bL[1][0] = t0[2]; bL[1][1] = t0[3];
                ldsm4(t1, base + 3 * TILE_BYTES + (boff1 ^ kx));
                bL[2][0] = t1[0]; bL[2][1] = t1[1];
                bL[3][0] = t1[2]; bL[3][1] = t1[3];
            }
#pragma unroll
            for (int mi = 0; mi < 4; mi++)
#pragma unroll
                for (int g = 0; g < 4; g++) {
                    mma_bf16(acc[mi][g], aH[mi], bH[g]);
                    mma_bf16(acc[mi][g], aH[mi], bL[g]);
                    mma_bf16(acc[mi][g], aL[mi], bH[g]);
                }
        }
    }

    // ---------------- epilogue
    const int r_in = lane >> 2;           // 0..7
    const int c_in = (lane & 3) * 2;      // 0,2,4,6
#pragma unroll
    for (int mi = 0; mi < 4; mi++) {
#pragma unroll
        for (int g = 0; g < 4; g++) {
            const int row0 = grow0 + wm * 64 + mi * 16 + r_in;
            const int col  = gcol0 + wn * 32 + g * 8 + c_in;
#pragma unroll
            for (int half = 0; half < 2; half++) {
                const int row = row0 + half * 8;
                float v0 = acc[mi][g][half * 2 + 0];
                float v1 = acc[mi][g][half * 2 + 1];
                const size_t off = (size_t)row * NDIM + col;
                if (GELU) {
                    v0 = 0.5f * v0 * (1.0f + erff(v0 * 0.70710678118654752f));
                    v1 = 0.5f * v1 * (1.0f + erff(v1 * 0.70710678118654752f));
                    __nv_bfloat16 h0 = __float2bfloat16(v0);
                    __nv_bfloat16 h1 = __float2bfloat16(v1);
                    __nv_bfloat16 l0 = __float2bfloat16(v0 - __bfloat162float(h0));
                    __nv_bfloat16 l1 = __float2bfloat16(v1 - __bfloat162float(h1));
                    *(__nv_bfloat162*)(out_hi + off) = __nv_bfloat162(h0, h1);
                    *(__nv_bfloat162*)(out_lo + off) = __nv_bfloat162(l0, l1);
                } else {
                    *(float2*)(out_f32 + off) = make_float2(v0, v1);
                }
            }
        }
    }
}

// ---------------------------------------------------------------- conversions
__global__ void split_kernel(const float* __restrict__ in,
                             __nv_bfloat16* __restrict__ hi,
                             __nv_bfloat16* __restrict__ lo) {
    const size_t i = (size_t)blockIdx.x * blockDim.x + threadIdx.x; // over n/4
    float4 v = ((const float4*)in)[i];
    __nv_bfloat16 h0 = __float2bfloat16(v.x), h1 = __float2bfloat16(v.y);
    __nv_bfloat16 h2 = __float2bfloat16(v.z), h3 = __float2bfloat16(v.w);
    __nv_bfloat16 l0 = __float2bfloat16(v.x - __bfloat162float(h0));
    __nv_bfloat16 l1 = __float2bfloat16(v.y - __bfloat162float(h1));
    __nv_bfloat16 l2 = __float2bfloat16(v.z - __bfloat162float(h2));
    __nv_bfloat16 l3 = __float2bfloat16(v.w - __bfloat162float(h3));
    ((__nv_bfloat162*)hi)[2 * i]     = __nv_bfloat162(h0, h1);
    ((__nv_bfloat162*)hi)[2 * i + 1] = __nv_bfloat162(h2, h3);
    ((__nv_bfloat162*)lo)[2 * i]     = __nv_bfloat162(l0, l1);
    ((__nv_bfloat162*)lo)[2 * i + 1] = __nv_bfloat162(l2, l3);
}

__global__ void scatter_split_kernel(const float* __restrict__ x,
                                     const int* __restrict__ scat,
                                     __nv_bfloat16* __restrict__ hi,
                                     __nv_bfloat16* __restrict__ lo) {
    const int p = blockIdx.x;                 // [0, M_TOT)
    const int d = scat[p];
    const float4* src = (const float4*)(x + (size_t)(p >> 1) * HIDDEN);
    __nv_bfloat162* dh = (__nv_bfloat162*)(hi + (size_t)d * HIDDEN);
    __nv_bfloat162* dl = (__nv_bfloat162*)(lo + (size_t)d * HIDDEN);
    for (int c = threadIdx.x; c < HIDDEN / 4; c += blockDim.x) {
        float4 v = src[c];
        __nv_bfloat16 h0 = __float2bfloat16(v.x), h1 = __float2bfloat16(v.y);
        __nv_bfloat16 h2 = __float2bfloat16(v.z), h3 = __float2bfloat16(v.w);
        dh[2 * c]     = __nv_bfloat162(h0, h1);
        dh[2 * c + 1] = __nv_bfloat162(h2, h3);
        dl[2 * c]     = __nv_bfloat162(__float2bfloat16(v.x - __bfloat162float(h0)),
                                       __float2bfloat16(v.y - __bfloat162float(h1)));
        dl[2 * c + 1] = __nv_bfloat162(__float2bfloat16(v.z - __bfloat162float(h2)),
                                       __float2bfloat16(v.w - __bfloat162float(h3)));
    }
}

__global__ void combine_kernel(const int* __restrict__ scat, float* __restrict__ out) {
    const int idx = blockIdx.x * blockDim.x + threadIdx.x;   // NTOK * HIDDEN/4
    const int t  = idx / (HIDDEN / 4);
    const int c4 = (idx % (HIDDEN / 4)) * 4;
    const int s0 = scat[t * TOPK + 0];
    const int s1 = scat[t * TOPK + 1];
    float4 v0 = *(const float4*)(g_y + (size_t)s0 * HIDDEN + c4);
    float4 v1 = *(const float4*)(g_y + (size_t)s1 * HIDDEN + c4);
    *(float4*)(out + (size_t)t * HIDDEN + c4) =
        make_float4(v0.x + v1.x, v0.y + v1.y, v0.z + v1.z, v0.w + v1.w);
}

// ---------------------------------------------------------------- host
extern "C" void kernel_launch(void* const* d_in, const int* in_sizes, int n_in,
                              void* d_out, int out_size) {
    const float* x    = (const float*)d_in[0];
    const float* w1   = (const float*)d_in[1];
    const float* w2   = (const float*)d_in[2];
    const int*   scat = (const int*)d_in[3];
    float* out = (float*)d_out;

    void *xs_hi, *xs_lo, *w1h, *w1l, *w2h, *w2l, *hh, *hl;
    cudaGetSymbolAddress(&xs_hi, g_xs_hi);
    cudaGetSymbolAddress(&xs_lo, g_xs_lo);
    cudaGetSymbolAddress(&w1h, g_w1_hi);
    cudaGetSymbolAddress(&w1l, g_w1_lo);
    cudaGetSymbolAddress(&w2h, g_w2_hi);
    cudaGetSymbolAddress(&w2l, g_w2_lo);
    cudaGetSymbolAddress(&hh, g_h_hi);
    cudaGetSymbolAddress(&hl, g_h_lo);
    float* ybuf = nullptr;
    cudaGetSymbolAddress((void**)&ybuf, g_y);

    static bool attr_set = false;
    cudaFuncSetAttribute(gemm_mma<true>,  cudaFuncAttributeMaxDynamicSharedMemorySize,
                         (int)SMEM_SZ);
    cudaFuncSetAttribute(gemm_mma<false>, cudaFuncAttributeMaxDynamicSharedMemorySize,
                         (int)SMEM_SZ);
    (void)attr_set;

    // conversions
    split_kernel<<<(NEXP * NDIM * KDIM) / (256 * 4), 256>>>(
        w1, (__nv_bfloat16*)w1h, (__nv_bfloat16*)w1l);
    split_kernel<<<(NEXP * NDIM * KDIM) / (256 * 4), 256>>>(
        w2, (__nv_bfloat16*)w2h, (__nv_bfloat16*)w2l);
    scatter_split_kernel<<<M_TOT, 256>>>(x, scat, (__nv_bfloat16*)xs_hi,
                                         (__nv_bfloat16*)xs_lo);

    // fc1: x_scat @ w1^T -> gelu -> h (bf16 hi/lo)
    gemm_mma<true><<<dim3(NDIM / BN, M_TOT / BM), 256, SMEM_SZ>>>(
        (const __nv_bfloat16*)xs_hi, (const __nv_bfloat16*)xs_lo,
        (const __nv_bfloat16*)w1h, (const __nv_bfloat16*)w1l,
        (__nv_bfloat16*)hh, (__nv_bfloat16*)hl, nullptr);

    // fc2: h @ w2^T -> y (f32)
    gemm_mma<false><<<dim3(HIDDEN / BN, M_TOT / BM), 256, SMEM_SZ>>>(
        (const __nv_bfloat16*)hh, (const __nv_bfloat16*)hl,
        (const __nv_bfloat16*)w2h, (const __nv_bfloat16*)w2l,
        nullptr, nullptr, ybuf);

    combine_kernel<<<(NTOK * (HIDDEN / 4)) / 256, 256>>>(scat, out);
}

// round 4
// speedup vs baseline: 3.2773x; 1.1630x over previous
#include <cuda_runtime.h>
#include <cuda_bf16.h>
#include <math.h>
#include <stdint.h>

// ---------------------------------------------------------------- constants
#define NTOK   8192
#define HIDDEN 2048
#define NEXP   8
#define TOPK   2
#define M_TOT  (NTOK * TOPK)      // 16384
#define CAP    (M_TOT / NEXP)     // 2048
#define KDIM   2048
#define NDIM   2048

constexpr int BM = 128, BN = 128, BK = 32;
constexpr int NS = 3;                          // pipeline stages
constexpr int NITER = KDIM / BK;               // 64
constexpr uint32_t TILE_BYTES  = 128 * 64;     // 8 KB: 128 rows x 32 bf16
constexpr uint32_t STAGE_BYTES = 4 * TILE_BYTES;   // Ah, Al, Bh, Bl = 32 KB
constexpr uint32_t SMEM_SZ     = NS * STAGE_BYTES; // 96 KB

// ---------------------------------------------------------------- scratch
__device__ __align__(1024) __nv_bfloat16 g_xs_hi[(size_t)M_TOT * KDIM];
__device__ __align__(1024) __nv_bfloat16 g_xs_lo[(size_t)M_TOT * KDIM];
__device__ __align__(1024) __nv_bfloat16 g_w1_hi[(size_t)NEXP * NDIM * KDIM];
__device__ __align__(1024) __nv_bfloat16 g_w1_lo[(size_t)NEXP * NDIM * KDIM];
__device__ __align__(1024) __nv_bfloat16 g_w2_hi[(size_t)NEXP * NDIM * KDIM];
__device__ __align__(1024) __nv_bfloat16 g_w2_lo[(size_t)NEXP * NDIM * KDIM];
__device__ __align__(1024) __nv_bfloat16 g_h_hi[(size_t)M_TOT * NDIM];
__device__ __align__(1024) __nv_bfloat16 g_h_lo[(size_t)M_TOT * NDIM];
__device__ __align__(1024) float         g_y[(size_t)M_TOT * HIDDEN];

// ---------------------------------------------------------------- helpers
__device__ __forceinline__ uint32_t smem_u32(const void* p) {
    uint32_t a;
    asm("{ .reg .u64 t; cvta.to.shared.u64 t, %1; cvt.u32.u64 %0, t; }"
        : "=r"(a) : "l"(p));
    return a;
}
__device__ __forceinline__ uint32_t sw128(uint32_t off) {
    return off ^ ((off >> 3) & 0x70);
}
__device__ __forceinline__ void cp16(uint32_t dst, const void* src) {
    asm volatile("cp.async.cg.shared.global [%0], [%1], 16;"
                 :: "r"(dst), "l"(src));
}
__device__ __forceinline__ void cp_commit() {
    asm volatile("cp.async.commit_group;");
}
template <int N>
__device__ __forceinline__ void cp_wait() {
    asm volatile("cp.async.wait_group %0;" :: "n"(N));
}
__device__ __forceinline__ void ldsm4(uint32_t* r, uint32_t addr) {
    asm volatile("ldmatrix.sync.aligned.m8n8.x4.shared.b16 {%0,%1,%2,%3}, [%4];"
                 : "=r"(r[0]), "=r"(r[1]), "=r"(r[2]), "=r"(r[3]) : "r"(addr));
}
__device__ __forceinline__ void mma_bf16(float* c, const uint32_t* a,
                                         const uint32_t* b) {
    asm volatile(
        "mma.sync.aligned.m16n8k16.row.col.f32.bf16.bf16.f32 "
        "{%0,%1,%2,%3},{%4,%5,%6,%7},{%8,%9},{%0,%1,%2,%3};"
        : "+f"(c[0]), "+f"(c[1]), "+f"(c[2]), "+f"(c[3])
        : "r"(a[0]), "r"(a[1]), "r"(a[2]), "r"(a[3]), "r"(b[0]), "r"(b[1]));
}

// ---------------------------------------------------------------- GEMM
// C[r,n] = sum_k A[r,k]*W[e,n,k]  via bf16 3-term split, fp32 accumulate.
template <bool GELU>
__global__ void __launch_bounds__(256, 2)
gemm_mma(const __nv_bfloat16* __restrict__ Ah, const __nv_bfloat16* __restrict__ Al,
         const __nv_bfloat16* __restrict__ Wh, const __nv_bfloat16* __restrict__ Wl,
         __nv_bfloat16* __restrict__ out_hi, __nv_bfloat16* __restrict__ out_lo,
         float* __restrict__ out_f32) {
    extern __shared__ __align__(1024) char smem[];
    const uint32_t sb = smem_u32(smem);
    const int tid  = threadIdx.x;
    const int lane = tid & 31;
    const int w    = tid >> 5;
    const int wm   = w & 1;       // M half (64 rows)
    const int wn   = w >> 1;      // N quarter (32 cols)
    const int grow0 = blockIdx.y * BM;
    const int gcol0 = blockIdx.x * BN;
    const int e     = grow0 / CAP;

    // ---- loader mapping: thread -> tile (Ah/Al/Bh/Bl), 8 chunks of 16B
    const int ltile = tid >> 6;          // 0..3
    const int lch   = tid & 63;          // chunk within first 16 rows
    const int lr0   = lch >> 2;          // row 0..15
    const int lc    = lch & 3;           // 16B chunk 0..3
    const uint32_t soff0 = (uint32_t)ltile * TILE_BYTES + sw128(lr0 * 64 + lc * 16);
    const __nv_bfloat16* gbase;
    if (ltile == 0)      gbase = Ah + (size_t)(grow0 + lr0) * KDIM + lc * 8;
    else if (ltile == 1) gbase = Al + (size_t)(grow0 + lr0) * KDIM + lc * 8;
    else if (ltile == 2) gbase = Wh + ((size_t)e * NDIM + gcol0 + lr0) * KDIM + lc * 8;
    else                 gbase = Wl + ((size_t)e * NDIM + gcol0 + lr0) * KDIM + lc * 8;

    // ---- ldmatrix per-lane offsets
    const int ar  = lane & 15;
    const int akh = lane >> 4;
    const uint32_t aoff = sw128(ar * 64 + akh * 16);     // + wm*4096 + mi*1024
    const int brn = lane & 7;
    const int bh  = (lane >> 3) & 1;
    const int bgs = lane >> 4;
    const int nrow0 = wn * 32 + bgs * 8 + brn;
    const uint32_t boff0 = sw128(nrow0 * 64 + bh * 16);
    const uint32_t boff1 = sw128((nrow0 + 16) * 64 + bh * 16);

    float acc[4][4][4];
#pragma unroll
    for (int i = 0; i < 4; i++)
#pragma unroll
        for (int j = 0; j < 4; j++)
#pragma unroll
            for (int k = 0; k < 4; k++) acc[i][j][k] = 0.f;

    auto load_stage = [&](int it) {
        if (it < NITER) {
            const uint32_t dst = sb + (uint32_t)(it % NS) * STAGE_BYTES + soff0;
            const __nv_bfloat16* src = gbase + it * BK;
#pragma unroll
            for (int i = 0; i < 8; i++)
                cp16(dst + i * 1024, src + (size_t)i * 16 * KDIM);
        }
        cp_commit();
    };

    load_stage(0);
    load_stage(1);

    for (int it = 0; it < NITER; it++) {
        cp_wait<1>();
        __syncthreads();
        load_stage(it + 2);

        const uint32_t base = sb + (uint32_t)(it % NS) * STAGE_BYTES;
#pragma unroll
        for (int kk = 0; kk < 2; kk++) {
            const uint32_t kx = (uint32_t)kk << 5;
            // B fragments first (shared across all mi)
            uint32_t bH[4][2], bL[4][2];
            {
                uint32_t t0[4], t1[4];
                ldsm4(t0, base + 2 * TILE_BYTES + (boff0 ^ kx));
                bH[0][0] = t0[0]; bH[0][1] = t0[1];
                bH[1][0] = t0[2]; bH[1][1] = t0[3];
                ldsm4(t1, base + 2 * TILE_BYTES + (boff1 ^ kx));
                bH[2][0] = t1[0]; bH[2][1] = t1[1];
                bH[3][0] = t1[2]; bH[3][1] = t1[3];
                ldsm4(t0, base + 3 * TILE_BYTES + (boff0 ^ kx));
                bL[0][0] = t0[0]; bL[0][1] = t0[1];
                bL[1][0] = t0[2]; bL[1][1] = t0[3];
                ldsm4(t1, base + 3 * TILE_BYTES + (boff1 ^ kx));
                bL[2][0] = t1[0]; bL[2][1] = t1[1];
                bL[3][0] = t1[2]; bL[3][1] = t1[3];
            }
            const uint32_t aaddr = base + wm * 4096 + (aoff ^ kx);
            // Stream A fragments per mi to keep register pressure low
#pragma unroll
            for (int mi = 0; mi < 4; mi++) {
                uint32_t aH[4], aL[4];
                ldsm4(aH, aaddr + mi * 1024);
                ldsm4(aL, aaddr + TILE_BYTES + mi * 1024);
#pragma unroll
                for (int g = 0; g < 4; g++) {
                    mma_bf16(acc[mi][g], aH, bH[g]);
                    mma_bf16(acc[mi][g], aH, bL[g]);
                    mma_bf16(acc[mi][g], aL, bH[g]);
                }
            }
        }
    }

    // ---------------- epilogue
    const int r_in = lane >> 2;           // 0..7
    const int c_in = (lane & 3) * 2;      // 0,2,4,6
#pragma unroll
    for (int mi = 0; mi < 4; mi++) {
#pragma unroll
        for (int g = 0; g < 4; g++) {
            const int row0 = grow0 + wm * 64 + mi * 16 + r_in;
            const int col  = gcol0 + wn * 32 + g * 8 + c_in;
#pragma unroll
            for (int half = 0; half < 2; half++) {
                const int row = row0 + half * 8;
                float v0 = acc[mi][g][half * 2 + 0];
                float v1 = acc[mi][g][half * 2 + 1];
                const size_t off = (size_t)row * NDIM + col;
                if (GELU) {
                    v0 = 0.5f * v0 * (1.0f + erff(v0 * 0.70710678118654752f));
                    v1 = 0.5f * v1 * (1.0f + erff(v1 * 0.70710678118654752f));
                    __nv_bfloat16 h0 = __float2bfloat16(v0);
                    __nv_bfloat16 h1 = __float2bfloat16(v1);
                    __nv_bfloat16 l0 = __float2bfloat16(v0 - __bfloat162float(h0));
                    __nv_bfloat16 l1 = __float2bfloat16(v1 - __bfloat162float(h1));
                    *(__nv_bfloat162*)(out_hi + off) = __nv_bfloat162(h0, h1);
                    *(__nv_bfloat162*)(out_lo + off) = __nv_bfloat162(l0, l1);
                } else {
                    *(float2*)(out_f32 + off) = make_float2(v0, v1);
                }
            }
        }
    }
}

// ---------------------------------------------------------------- conversions
__global__ void split_kernel(const float* __restrict__ in,
                             __nv_bfloat16* __restrict__ hi,
                             __nv_bfloat16* __restrict__ lo) {
    const size_t i = (size_t)blockIdx.x * blockDim.x + threadIdx.x; // over n/4
    float4 v = ((const float4*)in)[i];
    __nv_bfloat16 h0 = __float2bfloat16(v.x), h1 = __float2bfloat16(v.y);
    __nv_bfloat16 h2 = __float2bfloat16(v.z), h3 = __float2bfloat16(v.w);
    __nv_bfloat16 l0 = __float2bfloat16(v.x - __bfloat162float(h0));
    __nv_bfloat16 l1 = __float2bfloat16(v.y - __bfloat162float(h1));
    __nv_bfloat16 l2 = __float2bfloat16(v.z - __bfloat162float(h2));
    __nv_bfloat16 l3 = __float2bfloat16(v.w - __bfloat162float(h3));
    ((__nv_bfloat162*)hi)[2 * i]     = __nv_bfloat162(h0, h1);
    ((__nv_bfloat162*)hi)[2 * i + 1] = __nv_bfloat162(h2, h3);
    ((__nv_bfloat162*)lo)[2 * i]     = __nv_bfloat162(l0, l1);
    ((__nv_bfloat162*)lo)[2 * i + 1] = __nv_bfloat162(l2, l3);
}

__global__ void scatter_split_kernel(const float* __restrict__ x,
                                     const int* __restrict__ scat,
                                     __nv_bfloat16* __restrict__ hi,
                                     __nv_bfloat16* __restrict__ lo) {
    const int p = blockIdx.x;                 // [0, M_TOT)
    const int d = scat[p];
    const float4* src = (const float4*)(x + (size_t)(p >> 1) * HIDDEN);
    __nv_bfloat162* dh = (__nv_bfloat162*)(hi + (size_t)d * HIDDEN);
    __nv_bfloat162* dl = (__nv_bfloat162*)(lo + (size_t)d * HIDDEN);
    for (int c = threadIdx.x; c < HIDDEN / 4; c += blockDim.x) {
        float4 v = src[c];
        __nv_bfloat16 h0 = __float2bfloat16(v.x), h1 = __float2bfloat16(v.y);
        __nv_bfloat16 h2 = __float2bfloat16(v.z), h3 = __float2bfloat16(v.w);
        dh[2 * c]     = __nv_bfloat162(h0, h1);
        dh[2 * c + 1] = __nv_bfloat162(h2, h3);
        dl[2 * c]     = __nv_bfloat162(__float2bfloat16(v.x - __bfloat162float(h0)),
                                       __float2bfloat16(v.y - __bfloat162float(h1)));
        dl[2 * c + 1] = __nv_bfloat162(__float2bfloat16(v.z - __bfloat162float(h2)),
                                       __float2bfloat16(v.w - __bfloat162float(h3)));
    }
}

__global__ void combine_kernel(const int* __restrict__ scat, float* __restrict__ out) {
    const int idx = blockIdx.x * blockDim.x + threadIdx.x;   // NTOK * HIDDEN/4
    const int t  = idx / (HIDDEN / 4);
    const int c4 = (idx % (HIDDEN / 4)) * 4;
    const int s0 = scat[t * TOPK + 0];
    const int s1 = scat[t * TOPK + 1];
    float4 v0 = *(const float4*)(g_y + (size_t)s0 * HIDDEN + c4);
    float4 v1 = *(const float4*)(g_y + (size_t)s1 * HIDDEN + c4);
    *(float4*)(out + (size_t)t * HIDDEN + c4) =
        make_float4(v0.x + v1.x, v0.y + v1.y, v0.z + v1.z, v0.w + v1.w);
}

// ---------------------------------------------------------------- host
extern "C" void kernel_launch(void* const* d_in, const int* in_sizes, int n_in,
                              void* d_out, int out_size) {
    const float* x    = (const float*)d_in[0];
    const float* w1   = (const float*)d_in[1];
    const float* w2   = (const float*)d_in[2];
    const int*   scat = (const int*)d_in[3];
    float* out = (float*)d_out;

    void *xs_hi, *xs_lo, *w1h, *w1l, *w2h, *w2l, *hh, *hl;
    cudaGetSymbolAddress(&xs_hi, g_xs_hi);
    cudaGetSymbolAddress(&xs_lo, g_xs_lo);
    cudaGetSymbolAddress(&w1h, g_w1_hi);
    cudaGetSymbolAddress(&w1l, g_w1_lo);
    cudaGetSymbolAddress(&w2h, g_w2_hi);
    cudaGetSymbolAddress(&w2l, g_w2_lo);
    cudaGetSymbolAddress(&hh, g_h_hi);
    cudaGetSymbolAddress(&hl, g_h_lo);
    float* ybuf = nullptr;
    cudaGetSymbolAddress((void**)&ybuf, g_y);

    cudaFuncSetAttribute(gemm_mma<true>,  cudaFuncAttributeMaxDynamicSharedMemorySize,
                         (int)SMEM_SZ);
    cudaFuncSetAttribute(gemm_mma<false>, cudaFuncAttributeMaxDynamicSharedMemorySize,
                         (int)SMEM_SZ);

    // conversions
    split_kernel<<<(NEXP * NDIM * KDIM) / (256 * 4), 256>>>(
        w1, (__nv_bfloat16*)w1h, (__nv_bfloat16*)w1l);
    split_kernel<<<(NEXP * NDIM * KDIM) / (256 * 4), 256>>>(
        w2, (__nv_bfloat16*)w2h, (__nv_bfloat16*)w2l);
    scatter_split_kernel<<<M_TOT, 256>>>(x, scat, (__nv_bfloat16*)xs_hi,
                                         (__nv_bfloat16*)xs_lo);

    // fc1: x_scat @ w1^T -> gelu -> h (bf16 hi/lo)
    gemm_mma<true><<<dim3(NDIM / BN, M_TOT / BM), 256, SMEM_SZ>>>(
        (const __nv_bfloat16*)xs_hi, (const __nv_bfloat16*)xs_lo,
        (const __nv_bfloat16*)w1h, (const __nv_bfloat16*)w1l,
        (__nv_bfloat16*)hh, (__nv_bfloat16*)hl, nullptr);

    // fc2: h @ w2^T -> y (f32)
    gemm_mma<false><<<dim3(HIDDEN / BN, M_TOT / BM), 256, SMEM_SZ>>>(
        (const __nv_bfloat16*)hh, (const __nv_bfloat16*)hl,
        (const __nv_bfloat16*)w2h, (const __nv_bfloat16*)w2l,
        nullptr, nullptr, ybuf);

    combine_kernel<<<(NTOK * (HIDDEN / 4)) / 256, 256>>>(scat, out);
}